// round 15
// baseline (speedup 1.0000x reference)
#include <cuda_runtime.h>
#include <cuda_fp16.h>
#include <math.h>

#define NN 100000
#define NE 3200000
#define NG 64
#define D 32
#define INF 128
#define NPAD 102400   // 1024 threads * 100 counters

// ---- scratch (zero-initialized at module load; scan_all re-zeros per call) ----
__device__ __half g_rhsH[NN * D];   // fp16 gather buffer (64B rows)
__device__ float  g_self[NN * D];
__device__ float  g_h[NN * D];
__device__ float  g_pool[NG * D];
__device__ int    g_counts[NPAD];
__device__ int    g_offs[NPAD + 1];
__device__ int    g_cursor[NPAD];
__device__ int    g_csrc[NE];

// ------------------------------------------------------------------
__global__ void hist_kernel(const int* __restrict__ dst) {
    int i = blockIdx.x * blockDim.x + threadIdx.x;
    int b = i * 4;
    if (b < NE) {
        int4 d = *(const int4*)&dst[b];
        atomicAdd(&g_counts[d.x], 1);
        atomicAdd(&g_counts[d.y], 1);
        atomicAdd(&g_counts[d.z], 1);
        atomicAdd(&g_counts[d.w], 1);
    }
}

// single-block scan; also re-zeros g_counts and zeros g_pool for this call.
__global__ void __launch_bounds__(1024) scan_all() {
    const int CH = 100;
    int tid = threadIdx.x;
    int lane = tid & 31, wid = tid >> 5;
    int base = tid * CH;
    int s = 0;
    int cnt[CH];
#pragma unroll
    for (int i = 0; i < CH; i += 4) {
        int4 v = *(const int4*)&g_counts[base + i];
        cnt[i] = v.x; cnt[i + 1] = v.y; cnt[i + 2] = v.z; cnt[i + 3] = v.w;
        s += v.x + v.y + v.z + v.w;
    }
    int pre = s;
#pragma unroll
    for (int dd = 1; dd < 32; dd <<= 1) {
        int t = __shfl_up_sync(0xffffffffu, pre, dd);
        if (lane >= dd) pre += t;
    }
    __shared__ int wsum[32];
    if (lane == 31) wsum[wid] = pre;
    __syncthreads();
    if (wid == 0) {
        int v = wsum[lane];
        int p = v;
#pragma unroll
        for (int dd = 1; dd < 32; dd <<= 1) {
            int t = __shfl_up_sync(0xffffffffu, p, dd);
            if (lane >= dd) p += t;
        }
        wsum[lane] = p - v;
    }
    __syncthreads();
    int run = wsum[wid] + (pre - s);
    const int4 z4 = make_int4(0, 0, 0, 0);
#pragma unroll
    for (int i = 0; i < CH; i += 4) {
        int4 o;
        o.x = run; run += cnt[i];
        o.y = run; run += cnt[i + 1];
        o.z = run; run += cnt[i + 2];
        o.w = run; run += cnt[i + 3];
        *(int4*)&g_offs[base + i]   = o;
        *(int4*)&g_cursor[base + i] = o;
        *(int4*)&g_counts[base + i] = z4;
    }
    if (tid < NG * D / 2) *(float2*)&g_pool[tid * 2] = make_float2(0.f, 0.f);
}

__global__ void scatter_kernel(const int* __restrict__ src, const int* __restrict__ dst) {
    int i = blockIdx.x * blockDim.x + threadIdx.x;
    int b = i * 4;
    if (b < NE) {
        int4 s4 = *(const int4*)&src[b];
        int4 d4 = *(const int4*)&dst[b];
        int p;
        p = atomicAdd(&g_cursor[d4.x], 1); g_csrc[p] = s4.x;
        p = atomicAdd(&g_cursor[d4.y], 1); g_csrc[p] = s4.y;
        p = atomicAdd(&g_cursor[d4.z], 1); g_csrc[p] = s4.z;
        p = atomicAdd(&g_cursor[d4.w], 1); g_csrc[p] = s4.w;
    }
}

// ------------------------------------------------------------------
// fp16 GEMM core (R14-verified): thread owns 4 nodes x 16 cols as 4x8 half2 accs.
__device__ __forceinline__ void hgemm_ktile(const __half2 xs2[64][33],
                                            const __half2 Wsh2[32][32],
                                            int ng, int cg, __half2 acc2[4][8]) {
#pragma unroll 4
    for (int k = 0; k < 32; k++) {
        __half2 xh[4];
#pragma unroll
        for (int i = 0; i < 4; i++) xh[i] = xs2[ng * 4 + i][k];
        __align__(16) __half2 w2[8];
        const uint4* wp = (const uint4*)&Wsh2[k][cg * 8];
        *(uint4*)&w2[0] = wp[0];
        *(uint4*)&w2[4] = wp[1];
#pragma unroll
        for (int i = 0; i < 4; i++)
#pragma unroll
            for (int j = 0; j < 8; j++)
                acc2[i][j] = __hfma2(xh[i], w2[j], acc2[i][j]);
    }
}

__device__ __forceinline__ void hgemm_store(int n0, int ng, int cg, __half2 acc2[4][8]) {
    int c0 = cg * 16;
#pragma unroll
    for (int i = 0; i < 4; i++) {
        int n = n0 + ng * 4 + i;
        if (n >= NN) break;
        if (cg < 2) {
            *(uint4*)&g_rhsH[n * D + c0]     = *(uint4*)&acc2[i][0];
            *(uint4*)&g_rhsH[n * D + c0 + 8] = *(uint4*)&acc2[i][4];
        } else {
            float* dstp = &g_self[n * D + (c0 - 32)];
#pragma unroll
            for (int j = 0; j < 4; j++) {
                float2 a = __half22float2(acc2[i][2 * j]);
                float2 b = __half22float2(acc2[i][2 * j + 1]);
                *(float4*)&dstp[4 * j] = make_float4(a.x, a.y, b.x, b.y);
            }
        }
    }
}

// Layer 0: rhsH = fp16(x@Wn0), self = x@Ws0.  64 thr, 64 nodes/block.
__global__ void __launch_bounds__(64, 12) gemm0_kernel(const float* __restrict__ x,
                                                       const float* __restrict__ Wn0,
                                                       const float* __restrict__ Ws0) {
    __shared__ __half2 Wsh2[32][32];
    __shared__ __half2 xs2[64][33];
    int tid = threadIdx.x;
    int n0 = blockIdx.x * 64;
    int ng = tid >> 2, cg = tid & 3;
    __half2 acc2[4][8];
#pragma unroll
    for (int i = 0; i < 4; i++)
#pragma unroll
        for (int j = 0; j < 8; j++) acc2[i][j] = __float2half2_rn(0.f);

    for (int kt = 0; kt < 4; kt++) {
        __syncthreads();
        for (int idx = tid; idx < 32 * 32; idx += 64) {
            int k = idx >> 5, c2 = idx & 31;
            const float* srcw = (c2 < 16) ? &Wn0[kt * 1024 + k * 32 + 2 * c2]
                                          : &Ws0[kt * 1024 + k * 32 + 2 * (c2 - 16)];
            float2 wv = *(const float2*)srcw;
            Wsh2[k][c2] = __floats2half2_rn(wv.x, wv.y);
        }
        for (int idx = tid; idx < 64 * 32; idx += 64) {
            int nl = idx >> 5, j = idx & 31;
            int n = n0 + nl;
            float v = (n < NN) ? x[n * INF + kt * 32 + j] : 0.f;
            xs2[nl][j] = __float2half2_rn(v);
        }
        __syncthreads();
        hgemm_ktile(xs2, Wsh2, ng, cg, acc2);
    }
    hgemm_store(n0, ng, cg, acc2);
}

// Layers 1..3: rhsH = fp16(h@Wn_l), self = h@Ws_l  (K=32, input g_h).
__global__ void __launch_bounds__(64, 12) gemm_small_kernel(const float* __restrict__ Wn_l,
                                                            const float* __restrict__ Ws_l) {
    __shared__ __half2 Wsh2[32][32];
    __shared__ __half2 xs2[64][33];
    int tid = threadIdx.x;
    int n0 = blockIdx.x * 64;
    for (int idx = tid; idx < 32 * 32; idx += 64) {
        int k = idx >> 5, c2 = idx & 31;
        const float* srcw = (c2 < 16) ? &Wn_l[k * 32 + 2 * c2]
                                      : &Ws_l[k * 32 + 2 * (c2 - 16)];
        float2 wv = *(const float2*)srcw;
        Wsh2[k][c2] = __floats2half2_rn(wv.x, wv.y);
    }
    for (int idx = tid; idx < 64 * 32; idx += 64) {
        int nl = idx >> 5, j = idx & 31;
        int n = n0 + nl;
        float v = (n < NN) ? g_h[n * D + j] : 0.f;
        xs2[nl][j] = __float2half2_rn(v);
    }
    __syncthreads();
    int ng = tid >> 2, cg = tid & 3;
    __half2 acc2[4][8];
#pragma unroll
    for (int i = 0; i < 4; i++)
#pragma unroll
        for (int j = 0; j < 8; j++) acc2[i][j] = __float2half2_rn(0.f);
    hgemm_ktile(xs2, Wsh2, ng, cg, acc2);
    hgemm_store(n0, ng, cg, acc2);
}

// ------------------------------------------------------------------
// Aggregation: warp per node; 32 edges per main iter, 4-deep HADD2 tree,
// fp32 carry across iterations. eg = lane>>2 (edge slot), q = lane&3 (dims).
__device__ __forceinline__ void acc8(uint4 v, float* f) {
    const __half2* h = (const __half2*)&v;
#pragma unroll
    for (int j = 0; j < 4; j++) {
        float2 t = __half22float2(h[j]);
        f[2 * j]     += t.x;
        f[2 * j + 1] += t.y;
    }
}

__global__ void __launch_bounds__(256) agg_kernel(const float* __restrict__ bn) {
    int tid = threadIdx.x;
    int w = (blockIdx.x * blockDim.x + tid) >> 5;
    if (w >= NN) return;
    int lane = tid & 31;
    int eg = lane >> 2, q = lane & 3;
    const uint4* __restrict__ rhs4 = (const uint4*)g_rhsH;

    int beg = g_offs[w], end = g_offs[w + 1];
    float f[8];
#pragma unroll
    for (int j = 0; j < 8; j++) f[j] = 0.f;

    int e = beg;
    while (e + 32 <= end) {
        int i0 = g_csrc[e + eg];
        int i1 = g_csrc[e + 8 + eg];
        int i2 = g_csrc[e + 16 + eg];
        int i3 = g_csrc[e + 24 + eg];
        uint4 v0 = rhs4[i0 * 4 + q];
        uint4 v1 = rhs4[i1 * 4 + q];
        uint4 v2 = rhs4[i2 * 4 + q];
        uint4 v3 = rhs4[i3 * 4 + q];
        const __half2* h0 = (const __half2*)&v0;
        const __half2* h1 = (const __half2*)&v1;
        const __half2* h2 = (const __half2*)&v2;
        const __half2* h3 = (const __half2*)&v3;
#pragma unroll
        for (int j = 0; j < 4; j++) {
            __half2 s01 = __hadd2(h0[j], h1[j]);
            __half2 s23 = __hadd2(h2[j], h3[j]);
            __half2 s = __hadd2(s01, s23);     // 4-deep fp16 tree: overflow-safe
            float2 t = __half22float2(s);
            f[2 * j]     += t.x;
            f[2 * j + 1] += t.y;
        }
        e += 32;
    }
    while (e + 8 <= end) {
        int s = g_csrc[e + eg];
        uint4 v = rhs4[s * 4 + q];
        acc8(v, f);
        e += 8;
    }
    int rem = end - e;
    if (eg < rem) {
        int s = g_csrc[e + eg];
        uint4 v = rhs4[s * 4 + q];
        acc8(v, f);
    }

#pragma unroll
    for (int j = 0; j < 8; j++) {
        f[j] += __shfl_xor_sync(0xffffffffu, f[j], 4);
        f[j] += __shfl_xor_sync(0xffffffffu, f[j], 8);
        f[j] += __shfl_xor_sync(0xffffffffu, f[j], 16);
    }

    if (lane < 4) {
        int base = w * D + 8 * lane;
        float4 s0 = *(const float4*)&g_self[base];
        float4 s1 = *(const float4*)&g_self[base + 4];
        float4 b0 = *(const float4*)&bn[8 * lane];
        float4 b1 = *(const float4*)&bn[8 * lane + 4];
        float4 o0, o1;
        o0.x = fmaxf(f[0] + s0.x + b0.x, 0.f);
        o0.y = fmaxf(f[1] + s0.y + b0.y, 0.f);
        o0.z = fmaxf(f[2] + s0.z + b0.z, 0.f);
        o0.w = fmaxf(f[3] + s0.w + b0.w, 0.f);
        o1.x = fmaxf(f[4] + s1.x + b1.x, 0.f);
        o1.y = fmaxf(f[5] + s1.y + b1.y, 0.f);
        o1.z = fmaxf(f[6] + s1.z + b1.z, 0.f);
        o1.w = fmaxf(f[7] + s1.w + b1.w, 0.f);
        *(float4*)&g_h[base]     = o0;
        *(float4*)&g_h[base + 4] = o1;
    }
}

// ------------------------------------------------------------------
__global__ void __launch_bounds__(256) pool_kernel(const int* __restrict__ gid) {
    __shared__ float ps[NG * D];
    int tid = threadIdx.x;
    for (int i = tid; i < NG * D; i += 256) ps[i] = 0.f;
    __syncthreads();
    int d = tid & 31;
    int base = blockIdx.x * 1024;
    for (int i = tid >> 5; i < 1024; i += 8) {
        int n = base + i;
        if (n < NN) atomicAdd(&ps[gid[n] * D + d], g_h[n * D + d]);
    }
    __syncthreads();
    for (int i = tid; i < NG * D; i += 256) {
        float v = ps[i];
        if (v != 0.f) atomicAdd(&g_pool[i], v);
    }
}

__global__ void mlp_kernel(const float* __restrict__ Wfc1, const float* __restrict__ bfc1,
                           const float* __restrict__ Wout, const float* __restrict__ bout,
                           float* __restrict__ out) {
    int g = threadIdx.x;
    if (g >= NG) return;
    float hv[D];
#pragma unroll
    for (int k = 0; k < D; k++) hv[k] = g_pool[g * D + k];
    float h2[8];
#pragma unroll
    for (int j = 0; j < 8; j++) {
        float s = bfc1[j];
#pragma unroll
        for (int k = 0; k < D; k++) s = fmaf(hv[k], Wfc1[k * 8 + j], s);
        h2[j] = fmaxf(s, 0.f);
    }
    float o[4];
    float m = -1e30f;
#pragma unroll
    for (int j = 0; j < 4; j++) {
        float s = bout[j];
#pragma unroll
        for (int k = 0; k < 8; k++) s = fmaf(h2[k], Wout[k * 4 + j], s);
        o[j] = fmaxf(s, 0.f);
        if (o[j] > m) m = o[j];
    }
    float e[4]; float sum = 0.f;
#pragma unroll
    for (int j = 0; j < 4; j++) { e[j] = expf(o[j] - m); sum += e[j]; }
#pragma unroll
    for (int j = 0; j < 4; j++) out[g * 4 + j] = e[j] / sum;
}

// ------------------------------------------------------------------
extern "C" void kernel_launch(void* const* d_in, const int* in_sizes, int n_in,
                              void* d_out, int out_size) {
    const float* x    = (const float*)d_in[0];
    const float* Wn0  = (const float*)d_in[1];
    const float* bn0  = (const float*)d_in[2];
    const float* Ws0  = (const float*)d_in[3];
    const float* Wn   = (const float*)d_in[4];
    const float* bn   = (const float*)d_in[5];
    const float* Ws   = (const float*)d_in[6];
    const float* Wfc1 = (const float*)d_in[7];
    const float* bfc1 = (const float*)d_in[8];
    const float* Wout = (const float*)d_in[9];
    const float* bout = (const float*)d_in[10];
    const int*   src  = (const int*)d_in[11];
    const int*   dst  = (const int*)d_in[12];
    const int*   gid  = (const int*)d_in[13];
    float* out = (float*)d_out;

    // Fork a side stream so the CSR build overlaps gemm0.
    cudaStream_t s2;
    cudaEvent_t ev_fork, ev_join;
    cudaStreamCreateWithFlags(&s2, cudaStreamNonBlocking);
    cudaEventCreateWithFlags(&ev_fork, cudaEventDisableTiming);
    cudaEventCreateWithFlags(&ev_join, cudaEventDisableTiming);

    cudaEventRecord(ev_fork, 0);
    cudaStreamWaitEvent(s2, ev_fork, 0);

    hist_kernel<<<(NE / 4 + 255) / 256, 256, 0, s2>>>(dst);
    scan_all<<<1, 1024, 0, s2>>>();
    scatter_kernel<<<(NE / 4 + 255) / 256, 256, 0, s2>>>(src, dst);
    cudaEventRecord(ev_join, s2);

    gemm0_kernel<<<(NN + 63) / 64, 64>>>(x, Wn0, Ws0);

    cudaStreamWaitEvent(0, ev_join, 0);

    agg_kernel<<<(NN * 32 + 255) / 256, 256>>>(bn0);
    for (int l = 0; l < 3; l++) {
        gemm_small_kernel<<<(NN + 63) / 64, 64>>>(Wn + l * D * D, Ws + l * D * D);
        agg_kernel<<<(NN * 32 + 255) / 256, 256>>>(bn + l * D);
    }

    pool_kernel<<<(NN + 1023) / 1024, 256>>>(gid);
    mlp_kernel<<<1, 64>>>(Wfc1, bfc1, Wout, bout, out);
    // stream/events intentionally not destroyed (capture-safe; ~3 calls total)
}

// round 16
// speedup vs baseline: 1.1003x; 1.1003x over previous
#include <cuda_runtime.h>
#include <cuda_fp16.h>
#include <math.h>

#define NN 100000
#define NE 3200000
#define NG 64
#define D 32
#define INF 128
#define NPAD 102400   // 1024 threads * 100 counters

// ---- scratch (zero-initialized at module load; scan_all re-zeros per call) ----
__device__ __half g_rhsH[NN * D];   // fp16 gather buffer (64B rows)
__device__ float  g_self[NN * D];
__device__ float  g_h[NN * D];
__device__ float  g_pool[NG * D];
__device__ int    g_counts[NPAD];
__device__ int    g_offs[NPAD + 1];
__device__ int    g_cursor[NPAD];
__device__ int    g_csrc[NE];

// ------------------------------------------------------------------
__global__ void hist_kernel(const int* __restrict__ dst) {
    int i = blockIdx.x * blockDim.x + threadIdx.x;
    int b = i * 4;
    if (b < NE) {
        int4 d = *(const int4*)&dst[b];
        atomicAdd(&g_counts[d.x], 1);
        atomicAdd(&g_counts[d.y], 1);
        atomicAdd(&g_counts[d.z], 1);
        atomicAdd(&g_counts[d.w], 1);
    }
}

// single-block scan; also re-zeros g_counts and zeros g_pool for this call.
__global__ void __launch_bounds__(1024) scan_all() {
    const int CH = 100;
    int tid = threadIdx.x;
    int lane = tid & 31, wid = tid >> 5;
    int base = tid * CH;
    int s = 0;
    int cnt[CH];
#pragma unroll
    for (int i = 0; i < CH; i += 4) {
        int4 v = *(const int4*)&g_counts[base + i];
        cnt[i] = v.x; cnt[i + 1] = v.y; cnt[i + 2] = v.z; cnt[i + 3] = v.w;
        s += v.x + v.y + v.z + v.w;
    }
    int pre = s;
#pragma unroll
    for (int dd = 1; dd < 32; dd <<= 1) {
        int t = __shfl_up_sync(0xffffffffu, pre, dd);
        if (lane >= dd) pre += t;
    }
    __shared__ int wsum[32];
    if (lane == 31) wsum[wid] = pre;
    __syncthreads();
    if (wid == 0) {
        int v = wsum[lane];
        int p = v;
#pragma unroll
        for (int dd = 1; dd < 32; dd <<= 1) {
            int t = __shfl_up_sync(0xffffffffu, p, dd);
            if (lane >= dd) p += t;
        }
        wsum[lane] = p - v;
    }
    __syncthreads();
    int run = wsum[wid] + (pre - s);
    const int4 z4 = make_int4(0, 0, 0, 0);
#pragma unroll
    for (int i = 0; i < CH; i += 4) {
        int4 o;
        o.x = run; run += cnt[i];
        o.y = run; run += cnt[i + 1];
        o.z = run; run += cnt[i + 2];
        o.w = run; run += cnt[i + 3];
        *(int4*)&g_offs[base + i]   = o;
        *(int4*)&g_cursor[base + i] = o;
        *(int4*)&g_counts[base + i] = z4;
    }
    if (tid < NG * D / 2) *(float2*)&g_pool[tid * 2] = make_float2(0.f, 0.f);
}

__global__ void scatter_kernel(const int* __restrict__ src, const int* __restrict__ dst) {
    int i = blockIdx.x * blockDim.x + threadIdx.x;
    int b = i * 4;
    if (b < NE) {
        int4 s4 = *(const int4*)&src[b];
        int4 d4 = *(const int4*)&dst[b];
        int p;
        p = atomicAdd(&g_cursor[d4.x], 1); g_csrc[p] = s4.x;
        p = atomicAdd(&g_cursor[d4.y], 1); g_csrc[p] = s4.y;
        p = atomicAdd(&g_cursor[d4.z], 1); g_csrc[p] = s4.z;
        p = atomicAdd(&g_cursor[d4.w], 1); g_csrc[p] = s4.w;
    }
}

// ------------------------------------------------------------------
// fp16 GEMM core (R14-verified): thread owns 4 nodes x 16 cols as 4x8 half2 accs.
__device__ __forceinline__ void hgemm_ktile(const __half2 xs2[64][33],
                                            const __half2 Wsh2[32][32],
                                            int ng, int cg, __half2 acc2[4][8]) {
#pragma unroll 4
    for (int k = 0; k < 32; k++) {
        __half2 xh[4];
#pragma unroll
        for (int i = 0; i < 4; i++) xh[i] = xs2[ng * 4 + i][k];
        __align__(16) __half2 w2[8];
        const uint4* wp = (const uint4*)&Wsh2[k][cg * 8];
        *(uint4*)&w2[0] = wp[0];
        *(uint4*)&w2[4] = wp[1];
#pragma unroll
        for (int i = 0; i < 4; i++)
#pragma unroll
            for (int j = 0; j < 8; j++)
                acc2[i][j] = __hfma2(xh[i], w2[j], acc2[i][j]);
    }
}

__device__ __forceinline__ void hgemm_store(int n0, int ng, int cg, __half2 acc2[4][8]) {
    int c0 = cg * 16;
#pragma unroll
    for (int i = 0; i < 4; i++) {
        int n = n0 + ng * 4 + i;
        if (n >= NN) break;
        if (cg < 2) {
            *(uint4*)&g_rhsH[n * D + c0]     = *(uint4*)&acc2[i][0];
            *(uint4*)&g_rhsH[n * D + c0 + 8] = *(uint4*)&acc2[i][4];
        } else {
            float* dstp = &g_self[n * D + (c0 - 32)];
#pragma unroll
            for (int j = 0; j < 4; j++) {
                float2 a = __half22float2(acc2[i][2 * j]);
                float2 b = __half22float2(acc2[i][2 * j + 1]);
                *(float4*)&dstp[4 * j] = make_float4(a.x, a.y, b.x, b.y);
            }
        }
    }
}

// Layer 0: rhsH = fp16(x@Wn0), self = x@Ws0.  64 thr, 64 nodes/block.
__global__ void __launch_bounds__(64, 12) gemm0_kernel(const float* __restrict__ x,
                                                       const float* __restrict__ Wn0,
                                                       const float* __restrict__ Ws0) {
    __shared__ __half2 Wsh2[32][32];
    __shared__ __half2 xs2[64][33];
    int tid = threadIdx.x;
    int n0 = blockIdx.x * 64;
    int ng = tid >> 2, cg = tid & 3;
    __half2 acc2[4][8];
#pragma unroll
    for (int i = 0; i < 4; i++)
#pragma unroll
        for (int j = 0; j < 8; j++) acc2[i][j] = __float2half2_rn(0.f);

    for (int kt = 0; kt < 4; kt++) {
        __syncthreads();
        for (int idx = tid; idx < 32 * 32; idx += 64) {
            int k = idx >> 5, c2 = idx & 31;
            const float* srcw = (c2 < 16) ? &Wn0[kt * 1024 + k * 32 + 2 * c2]
                                          : &Ws0[kt * 1024 + k * 32 + 2 * (c2 - 16)];
            float2 wv = *(const float2*)srcw;
            Wsh2[k][c2] = __floats2half2_rn(wv.x, wv.y);
        }
        for (int idx = tid; idx < 64 * 32; idx += 64) {
            int nl = idx >> 5, j = idx & 31;
            int n = n0 + nl;
            float v = (n < NN) ? x[n * INF + kt * 32 + j] : 0.f;
            xs2[nl][j] = __float2half2_rn(v);
        }
        __syncthreads();
        hgemm_ktile(xs2, Wsh2, ng, cg, acc2);
    }
    hgemm_store(n0, ng, cg, acc2);
}

// Layers 1..3: rhsH = fp16(h@Wn_l), self = h@Ws_l  (K=32, input g_h).
__global__ void __launch_bounds__(64, 12) gemm_small_kernel(const float* __restrict__ Wn_l,
                                                            const float* __restrict__ Ws_l) {
    __shared__ __half2 Wsh2[32][32];
    __shared__ __half2 xs2[64][33];
    int tid = threadIdx.x;
    int n0 = blockIdx.x * 64;
    for (int idx = tid; idx < 32 * 32; idx += 64) {
        int k = idx >> 5, c2 = idx & 31;
        const float* srcw = (c2 < 16) ? &Wn_l[k * 32 + 2 * c2]
                                      : &Ws_l[k * 32 + 2 * (c2 - 16)];
        float2 wv = *(const float2*)srcw;
        Wsh2[k][c2] = __floats2half2_rn(wv.x, wv.y);
    }
    for (int idx = tid; idx < 64 * 32; idx += 64) {
        int nl = idx >> 5, j = idx & 31;
        int n = n0 + nl;
        float v = (n < NN) ? g_h[n * D + j] : 0.f;
        xs2[nl][j] = __float2half2_rn(v);
    }
    __syncthreads();
    int ng = tid >> 2, cg = tid & 3;
    __half2 acc2[4][8];
#pragma unroll
    for (int i = 0; i < 4; i++)
#pragma unroll
        for (int j = 0; j < 8; j++) acc2[i][j] = __float2half2_rn(0.f);
    hgemm_ktile(xs2, Wsh2, ng, cg, acc2);
    hgemm_store(n0, ng, cg, acc2);
}

// ------------------------------------------------------------------
// Aggregation gather core (R14-verified): warp per node; 8 edges per warp-LDG,
// 2-deep HADD2 pairing. eg = lane>>2 (edge slot), q = lane&3 (dims 8q..8q+7).
__device__ __forceinline__ void acc8(uint4 v, float* f) {
    const __half2* h = (const __half2*)&v;
#pragma unroll
    for (int j = 0; j < 4; j++) {
        float2 t = __half22float2(h[j]);
        f[2 * j]     += t.x;
        f[2 * j + 1] += t.y;
    }
}

__device__ __forceinline__ void acc8_pair(uint4 a, uint4 b, float* f) {
    const __half2* ha = (const __half2*)&a;
    const __half2* hb = (const __half2*)&b;
#pragma unroll
    for (int j = 0; j < 4; j++) {
        __half2 s = __hadd2(ha[j], hb[j]);   // 2-way fp16 sum: overflow-safe
        float2 t = __half22float2(s);
        f[2 * j]     += t.x;
        f[2 * j + 1] += t.y;
    }
}

__device__ __forceinline__ void gather_node(int w, int lane, float* f) {
    int eg = lane >> 2, q = lane & 3;
    const uint4* __restrict__ rhs4 = (const uint4*)g_rhsH;
    int beg = g_offs[w], end = g_offs[w + 1];
    int e = beg;
    while (e + 16 <= end) {
        int s0 = g_csrc[e + eg];
        int s1 = g_csrc[e + 8 + eg];
        uint4 v0 = rhs4[s0 * 4 + q];
        uint4 v1 = rhs4[s1 * 4 + q];
        acc8_pair(v0, v1, f);
        e += 16;
    }
    while (e + 8 <= end) {
        int s = g_csrc[e + eg];
        uint4 v = rhs4[s * 4 + q];
        acc8(v, f);
        e += 8;
    }
    int rem = end - e;
    if (eg < rem) {
        int s = g_csrc[e + eg];
        uint4 v = rhs4[s * 4 + q];
        acc8(v, f);
    }
#pragma unroll
    for (int j = 0; j < 8; j++) {
        f[j] += __shfl_xor_sync(0xffffffffu, f[j], 4);
        f[j] += __shfl_xor_sync(0xffffffffu, f[j], 8);
        f[j] += __shfl_xor_sync(0xffffffffu, f[j], 16);
    }
}

// Layers 0..2: agg -> g_h
__global__ void __launch_bounds__(256) agg_kernel(const float* __restrict__ bn) {
    int tid = threadIdx.x;
    int w = (blockIdx.x * blockDim.x + tid) >> 5;
    if (w >= NN) return;
    int lane = tid & 31;
    float f[8];
#pragma unroll
    for (int j = 0; j < 8; j++) f[j] = 0.f;
    gather_node(w, lane, f);

    if (lane < 4) {
        int base = w * D + 8 * lane;
        float4 s0 = *(const float4*)&g_self[base];
        float4 s1 = *(const float4*)&g_self[base + 4];
        float4 b0 = *(const float4*)&bn[8 * lane];
        float4 b1 = *(const float4*)&bn[8 * lane + 4];
        float4 o0, o1;
        o0.x = fmaxf(f[0] + s0.x + b0.x, 0.f);
        o0.y = fmaxf(f[1] + s0.y + b0.y, 0.f);
        o0.z = fmaxf(f[2] + s0.z + b0.z, 0.f);
        o0.w = fmaxf(f[3] + s0.w + b0.w, 0.f);
        o1.x = fmaxf(f[4] + s1.x + b1.x, 0.f);
        o1.y = fmaxf(f[5] + s1.y + b1.y, 0.f);
        o1.z = fmaxf(f[6] + s1.z + b1.z, 0.f);
        o1.w = fmaxf(f[7] + s1.w + b1.w, 0.f);
        *(float4*)&g_h[base]     = o0;
        *(float4*)&g_h[base + 4] = o1;
    }
}

// Layer 3: agg fused with per-graph sum pooling (no g_h round-trip).
// Grid is exactly 12500x256 = 100000 warps, so every warp has w < NN and the
// block-wide barriers below are uniformly executed.
__global__ void __launch_bounds__(256) agg_pool_kernel(const float* __restrict__ bn,
                                                       const int* __restrict__ gid) {
    __shared__ float ps[NG * D];
    int tid = threadIdx.x;
    for (int i = tid; i < NG * D; i += 256) ps[i] = 0.f;
    __syncthreads();

    int w = (blockIdx.x * blockDim.x + tid) >> 5;
    int lane = tid & 31;
    float f[8];
#pragma unroll
    for (int j = 0; j < 8; j++) f[j] = 0.f;
    gather_node(w, lane, f);

    if (lane < 4) {
        int base = w * D + 8 * lane;
        float4 s0 = *(const float4*)&g_self[base];
        float4 s1 = *(const float4*)&g_self[base + 4];
        float4 b0 = *(const float4*)&bn[8 * lane];
        float4 b1 = *(const float4*)&bn[8 * lane + 4];
        float* pp = &ps[gid[w] * D + 8 * lane];
        atomicAdd(&pp[0], fmaxf(f[0] + s0.x + b0.x, 0.f));
        atomicAdd(&pp[1], fmaxf(f[1] + s0.y + b0.y, 0.f));
        atomicAdd(&pp[2], fmaxf(f[2] + s0.z + b0.z, 0.f));
        atomicAdd(&pp[3], fmaxf(f[3] + s0.w + b0.w, 0.f));
        atomicAdd(&pp[4], fmaxf(f[4] + s1.x + b1.x, 0.f));
        atomicAdd(&pp[5], fmaxf(f[5] + s1.y + b1.y, 0.f));
        atomicAdd(&pp[6], fmaxf(f[6] + s1.z + b1.z, 0.f));
        atomicAdd(&pp[7], fmaxf(f[7] + s1.w + b1.w, 0.f));
    }
    __syncthreads();
    // flush nonzero entries (nodes sorted by graph id -> ~2 graphs per block)
    for (int i = tid; i < NG * D; i += 256) {
        float v = ps[i];
        if (v != 0.f) atomicAdd(&g_pool[i], v);
    }
}

// ------------------------------------------------------------------
__global__ void mlp_kernel(const float* __restrict__ Wfc1, const float* __restrict__ bfc1,
                           const float* __restrict__ Wout, const float* __restrict__ bout,
                           float* __restrict__ out) {
    int g = threadIdx.x;
    if (g >= NG) return;
    float hv[D];
#pragma unroll
    for (int k = 0; k < D; k++) hv[k] = g_pool[g * D + k];
    float h2[8];
#pragma unroll
    for (int j = 0; j < 8; j++) {
        float s = bfc1[j];
#pragma unroll
        for (int k = 0; k < D; k++) s = fmaf(hv[k], Wfc1[k * 8 + j], s);
        h2[j] = fmaxf(s, 0.f);
    }
    float o[4];
    float m = -1e30f;
#pragma unroll
    for (int j = 0; j < 4; j++) {
        float s = bout[j];
#pragma unroll
        for (int k = 0; k < 8; k++) s = fmaf(h2[k], Wout[k * 4 + j], s);
        o[j] = fmaxf(s, 0.f);
        if (o[j] > m) m = o[j];
    }
    float e[4]; float sum = 0.f;
#pragma unroll
    for (int j = 0; j < 4; j++) { e[j] = expf(o[j] - m); sum += e[j]; }
#pragma unroll
    for (int j = 0; j < 4; j++) out[g * 4 + j] = e[j] / sum;
}

// ------------------------------------------------------------------
extern "C" void kernel_launch(void* const* d_in, const int* in_sizes, int n_in,
                              void* d_out, int out_size) {
    const float* x    = (const float*)d_in[0];
    const float* Wn0  = (const float*)d_in[1];
    const float* bn0  = (const float*)d_in[2];
    const float* Ws0  = (const float*)d_in[3];
    const float* Wn   = (const float*)d_in[4];
    const float* bn   = (const float*)d_in[5];
    const float* Ws   = (const float*)d_in[6];
    const float* Wfc1 = (const float*)d_in[7];
    const float* bfc1 = (const float*)d_in[8];
    const float* Wout = (const float*)d_in[9];
    const float* bout = (const float*)d_in[10];
    const int*   src  = (const int*)d_in[11];
    const int*   dst  = (const int*)d_in[12];
    const int*   gid  = (const int*)d_in[13];
    float* out = (float*)d_out;

    // Fork a side stream so the CSR build overlaps gemm0.
    cudaStream_t s2;
    cudaEvent_t ev_fork, ev_join;
    cudaStreamCreateWithFlags(&s2, cudaStreamNonBlocking);
    cudaEventCreateWithFlags(&ev_fork, cudaEventDisableTiming);
    cudaEventCreateWithFlags(&ev_join, cudaEventDisableTiming);

    cudaEventRecord(ev_fork, 0);
    cudaStreamWaitEvent(s2, ev_fork, 0);

    hist_kernel<<<(NE / 4 + 255) / 256, 256, 0, s2>>>(dst);
    scan_all<<<1, 1024, 0, s2>>>();
    scatter_kernel<<<(NE / 4 + 255) / 256, 256, 0, s2>>>(src, dst);
    cudaEventRecord(ev_join, s2);

    gemm0_kernel<<<(NN + 63) / 64, 64>>>(x, Wn0, Ws0);

    cudaStreamWaitEvent(0, ev_join, 0);

    agg_kernel<<<(NN * 32 + 255) / 256, 256>>>(bn0);
    for (int l = 0; l < 2; l++) {
        gemm_small_kernel<<<(NN + 63) / 64, 64>>>(Wn + l * D * D, Ws + l * D * D);
        agg_kernel<<<(NN * 32 + 255) / 256, 256>>>(bn + l * D);
    }
    // layer 3: transform + fused agg+pool
    gemm_small_kernel<<<(NN + 63) / 64, 64>>>(Wn + 2 * D * D, Ws + 2 * D * D);
    agg_pool_kernel<<<NN * 32 / 256, 256>>>(bn + 2 * D, gid);

    mlp_kernel<<<1, 64>>>(Wfc1, bfc1, Wout, bout, out);
    // stream/events intentionally not destroyed (capture-safe; ~3 calls total)
}

// round 17
// speedup vs baseline: 1.2571x; 1.1425x over previous
#include <cuda_runtime.h>
#include <cuda_fp16.h>
#include <math.h>

#define NN 100000
#define NE 3200000
#define NG 64
#define D 32
#define INF 128
#define NPAD 102400   // 200 blocks * 512 threads
#define SCB 200       // scan blocks

// ---- scratch (zero-initialized at module load; scan kernels re-zero per call) ----
__device__ __half g_rhsH[NN * D];   // fp16 gather buffer (64B rows)
__device__ float  g_self[NN * D];
__device__ float  g_h[NN * D];
__device__ float  g_pool[NG * D];
__device__ int    g_counts[NPAD];
__device__ int    g_offs[NPAD + 1];
__device__ int    g_cursor[NPAD];
__device__ int    g_csrc[NE];
__device__ int    g_bsums[256];

// ------------------------------------------------------------------
__global__ void hist_kernel(const int* __restrict__ dst) {
    int i = blockIdx.x * blockDim.x + threadIdx.x;
    int b = i * 4;
    if (b < NE) {
        int4 d = *(const int4*)&dst[b];
        atomicAdd(&g_counts[d.x], 1);
        atomicAdd(&g_counts[d.y], 1);
        atomicAdd(&g_counts[d.z], 1);
        atomicAdd(&g_counts[d.w], 1);
    }
}

// Parallel scan, stage 1: block-local exclusive scan of 512 counters.
__global__ void __launch_bounds__(512) scan_part() {
    __shared__ int wsum[16];
    int tid = threadIdx.x;
    int lane = tid & 31, wid = tid >> 5;
    int i = blockIdx.x * 512 + tid;
    int v = g_counts[i];
    int pre = v;
#pragma unroll
    for (int dd = 1; dd < 32; dd <<= 1) {
        int t = __shfl_up_sync(0xffffffffu, pre, dd);
        if (lane >= dd) pre += t;
    }
    if (lane == 31) wsum[wid] = pre;
    __syncthreads();
    if (wid == 0 && lane < 16) {
        int s = wsum[lane];
        int p = s;
#pragma unroll
        for (int dd = 1; dd < 16; dd <<= 1) {
            int t = __shfl_up_sync(0xffffu, p, dd);
            if (lane >= dd) p += t;
        }
        wsum[lane] = p - s;   // exclusive warp base
        if (lane == 15) g_bsums[blockIdx.x] = p;   // block total
    }
    __syncthreads();
    g_offs[i] = wsum[wid] + (pre - v);   // block-local exclusive
}

// stage 2: exclusive scan of 200 block sums (1 block); also zero g_pool.
__global__ void __launch_bounds__(256) scan_mid() {
    __shared__ int wsum[8];
    int tid = threadIdx.x;
    int lane = tid & 31, wid = tid >> 5;
    int v = (tid < SCB) ? g_bsums[tid] : 0;
    int pre = v;
#pragma unroll
    for (int dd = 1; dd < 32; dd <<= 1) {
        int t = __shfl_up_sync(0xffffffffu, pre, dd);
        if (lane >= dd) pre += t;
    }
    if (lane == 31) wsum[wid] = pre;
    __syncthreads();
    if (wid == 0 && lane < 8) {
        int s = wsum[lane];
        int p = s;
#pragma unroll
        for (int dd = 1; dd < 8; dd <<= 1) {
            int t = __shfl_up_sync(0xffu, p, dd);
            if (lane >= dd) p += t;
        }
        wsum[lane] = p - s;
    }
    __syncthreads();
    if (tid < SCB) g_bsums[tid] = wsum[wid] + (pre - v);   // exclusive base
    // zero pool accumulator (2048 floats)
    for (int i = tid; i < NG * D; i += 256) g_pool[i] = 0.f;
}

// stage 3: add block base; init cursor; re-zero counts for next call.
__global__ void __launch_bounds__(512) scan_add() {
    int tid = threadIdx.x;
    int i = blockIdx.x * 512 + tid;
    int base = g_bsums[blockIdx.x];
    int o = g_offs[i] + base;
    g_offs[i] = o;
    g_cursor[i] = o;
    g_counts[i] = 0;
    if (blockIdx.x == SCB - 1 && tid == 511) g_offs[NPAD] = 0;  // unused pad
    if (i == NN) {}  // offs[NN] already correct: counts beyond NN are zero
}

__global__ void scatter_kernel(const int* __restrict__ src, const int* __restrict__ dst) {
    int i = blockIdx.x * blockDim.x + threadIdx.x;
    int b = i * 4;
    if (b < NE) {
        int4 s4 = *(const int4*)&src[b];
        int4 d4 = *(const int4*)&dst[b];
        int p;
        p = atomicAdd(&g_cursor[d4.x], 1); g_csrc[p] = s4.x;
        p = atomicAdd(&g_cursor[d4.y], 1); g_csrc[p] = s4.y;
        p = atomicAdd(&g_cursor[d4.z], 1); g_csrc[p] = s4.z;
        p = atomicAdd(&g_cursor[d4.w], 1); g_csrc[p] = s4.w;
    }
}

// ------------------------------------------------------------------
// fp16 GEMM core (R14-verified): thread owns 4 nodes x 16 cols as 4x8 half2 accs.
__device__ __forceinline__ void hgemm_ktile(const __half2 xs2[64][33],
                                            const __half2 Wsh2[32][32],
                                            int ng, int cg, __half2 acc2[4][8]) {
#pragma unroll 4
    for (int k = 0; k < 32; k++) {
        __half2 xh[4];
#pragma unroll
        for (int i = 0; i < 4; i++) xh[i] = xs2[ng * 4 + i][k];
        __align__(16) __half2 w2[8];
        const uint4* wp = (const uint4*)&Wsh2[k][cg * 8];
        *(uint4*)&w2[0] = wp[0];
        *(uint4*)&w2[4] = wp[1];
#pragma unroll
        for (int i = 0; i < 4; i++)
#pragma unroll
            for (int j = 0; j < 8; j++)
                acc2[i][j] = __hfma2(xh[i], w2[j], acc2[i][j]);
    }
}

__device__ __forceinline__ void hgemm_store(int n0, int ng, int cg, __half2 acc2[4][8]) {
    int c0 = cg * 16;
#pragma unroll
    for (int i = 0; i < 4; i++) {
        int n = n0 + ng * 4 + i;
        if (n >= NN) break;
        if (cg < 2) {
            *(uint4*)&g_rhsH[n * D + c0]     = *(uint4*)&acc2[i][0];
            *(uint4*)&g_rhsH[n * D + c0 + 8] = *(uint4*)&acc2[i][4];
        } else {
            float* dstp = &g_self[n * D + (c0 - 32)];
#pragma unroll
            for (int j = 0; j < 4; j++) {
                float2 a = __half22float2(acc2[i][2 * j]);
                float2 b = __half22float2(acc2[i][2 * j + 1]);
                *(float4*)&dstp[4 * j] = make_float4(a.x, a.y, b.x, b.y);
            }
        }
    }
}

// Layer 0: rhsH = fp16(x@Wn0), self = x@Ws0.  64 thr, 64 nodes/block.
__global__ void __launch_bounds__(64, 12) gemm0_kernel(const float* __restrict__ x,
                                                       const float* __restrict__ Wn0,
                                                       const float* __restrict__ Ws0) {
    __shared__ __half2 Wsh2[32][32];
    __shared__ __half2 xs2[64][33];
    int tid = threadIdx.x;
    int n0 = blockIdx.x * 64;
    int ng = tid >> 2, cg = tid & 3;
    __half2 acc2[4][8];
#pragma unroll
    for (int i = 0; i < 4; i++)
#pragma unroll
        for (int j = 0; j < 8; j++) acc2[i][j] = __float2half2_rn(0.f);

    for (int kt = 0; kt < 4; kt++) {
        __syncthreads();
        for (int idx = tid; idx < 32 * 32; idx += 64) {
            int k = idx >> 5, c2 = idx & 31;
            const float* srcw = (c2 < 16) ? &Wn0[kt * 1024 + k * 32 + 2 * c2]
                                          : &Ws0[kt * 1024 + k * 32 + 2 * (c2 - 16)];
            float2 wv = *(const float2*)srcw;
            Wsh2[k][c2] = __floats2half2_rn(wv.x, wv.y);
        }
        for (int idx = tid; idx < 64 * 32; idx += 64) {
            int nl = idx >> 5, j = idx & 31;
            int n = n0 + nl;
            float v = (n < NN) ? x[n * INF + kt * 32 + j] : 0.f;
            xs2[nl][j] = __float2half2_rn(v);
        }
        __syncthreads();
        hgemm_ktile(xs2, Wsh2, ng, cg, acc2);
    }
    hgemm_store(n0, ng, cg, acc2);
}

// Layers 1..3: rhsH = fp16(h@Wn_l), self = h@Ws_l  (K=32, input g_h).
// Reg-capped to 64 (forces 16 CTAs/SM target -> higher occupancy; on critical path).
__global__ void __launch_bounds__(64, 16) gemm_small_kernel(const float* __restrict__ Wn_l,
                                                            const float* __restrict__ Ws_l) {
    __shared__ __half2 Wsh2[32][32];
    __shared__ __half2 xs2[64][33];
    int tid = threadIdx.x;
    int n0 = blockIdx.x * 64;
    for (int idx = tid; idx < 32 * 32; idx += 64) {
        int k = idx >> 5, c2 = idx & 31;
        const float* srcw = (c2 < 16) ? &Wn_l[k * 32 + 2 * c2]
                                      : &Ws_l[k * 32 + 2 * (c2 - 16)];
        float2 wv = *(const float2*)srcw;
        Wsh2[k][c2] = __floats2half2_rn(wv.x, wv.y);
    }
    for (int idx = tid; idx < 64 * 32; idx += 64) {
        int nl = idx >> 5, j = idx & 31;
        int n = n0 + nl;
        float v = (n < NN) ? g_h[n * D + j] : 0.f;
        xs2[nl][j] = __float2half2_rn(v);
    }
    __syncthreads();
    int ng = tid >> 2, cg = tid & 3;
    __half2 acc2[4][8];
#pragma unroll
    for (int i = 0; i < 4; i++)
#pragma unroll
        for (int j = 0; j < 8; j++) acc2[i][j] = __float2half2_rn(0.f);
    hgemm_ktile(xs2, Wsh2, ng, cg, acc2);
    hgemm_store(n0, ng, cg, acc2);
}

// ------------------------------------------------------------------
// Aggregation gather core (R14-verified): warp per node; 8 edges per warp-LDG,
// 2-deep HADD2 pairing. eg = lane>>2 (edge slot), q = lane&3 (dims 8q..8q+7).
__device__ __forceinline__ void acc8(uint4 v, float* f) {
    const __half2* h = (const __half2*)&v;
#pragma unroll
    for (int j = 0; j < 4; j++) {
        float2 t = __half22float2(h[j]);
        f[2 * j]     += t.x;
        f[2 * j + 1] += t.y;
    }
}

__device__ __forceinline__ void acc8_pair(uint4 a, uint4 b, float* f) {
    const __half2* ha = (const __half2*)&a;
    const __half2* hb = (const __half2*)&b;
#pragma unroll
    for (int j = 0; j < 4; j++) {
        __half2 s = __hadd2(ha[j], hb[j]);   // 2-way fp16 sum: overflow-safe
        float2 t = __half22float2(s);
        f[2 * j]     += t.x;
        f[2 * j + 1] += t.y;
    }
}

__device__ __forceinline__ void gather_node(int w, int lane, float* f) {
    int eg = lane >> 2, q = lane & 3;
    const uint4* __restrict__ rhs4 = (const uint4*)g_rhsH;
    int beg = g_offs[w], end = g_offs[w + 1];
    int e = beg;
    while (e + 16 <= end) {
        int s0 = g_csrc[e + eg];
        int s1 = g_csrc[e + 8 + eg];
        uint4 v0 = rhs4[s0 * 4 + q];
        uint4 v1 = rhs4[s1 * 4 + q];
        acc8_pair(v0, v1, f);
        e += 16;
    }
    while (e + 8 <= end) {
        int s = g_csrc[e + eg];
        uint4 v = rhs4[s * 4 + q];
        acc8(v, f);
        e += 8;
    }
    int rem = end - e;
    if (eg < rem) {
        int s = g_csrc[e + eg];
        uint4 v = rhs4[s * 4 + q];
        acc8(v, f);
    }
#pragma unroll
    for (int j = 0; j < 8; j++) {
        f[j] += __shfl_xor_sync(0xffffffffu, f[j], 4);
        f[j] += __shfl_xor_sync(0xffffffffu, f[j], 8);
        f[j] += __shfl_xor_sync(0xffffffffu, f[j], 16);
    }
}

// Layers 0..2: agg -> g_h
__global__ void __launch_bounds__(256) agg_kernel(const float* __restrict__ bn) {
    int tid = threadIdx.x;
    int w = (blockIdx.x * blockDim.x + tid) >> 5;
    if (w >= NN) return;
    int lane = tid & 31;
    float f[8];
#pragma unroll
    for (int j = 0; j < 8; j++) f[j] = 0.f;
    gather_node(w, lane, f);

    if (lane < 4) {
        int base = w * D + 8 * lane;
        float4 s0 = *(const float4*)&g_self[base];
        float4 s1 = *(const float4*)&g_self[base + 4];
        float4 b0 = *(const float4*)&bn[8 * lane];
        float4 b1 = *(const float4*)&bn[8 * lane + 4];
        float4 o0, o1;
        o0.x = fmaxf(f[0] + s0.x + b0.x, 0.f);
        o0.y = fmaxf(f[1] + s0.y + b0.y, 0.f);
        o0.z = fmaxf(f[2] + s0.z + b0.z, 0.f);
        o0.w = fmaxf(f[3] + s0.w + b0.w, 0.f);
        o1.x = fmaxf(f[4] + s1.x + b1.x, 0.f);
        o1.y = fmaxf(f[5] + s1.y + b1.y, 0.f);
        o1.z = fmaxf(f[6] + s1.z + b1.z, 0.f);
        o1.w = fmaxf(f[7] + s1.w + b1.w, 0.f);
        *(float4*)&g_h[base]     = o0;
        *(float4*)&g_h[base + 4] = o1;
    }
}

// Layer 3: agg fused with per-graph sum pooling (R16-verified).
__global__ void __launch_bounds__(256) agg_pool_kernel(const float* __restrict__ bn,
                                                       const int* __restrict__ gid) {
    __shared__ float ps[NG * D];
    int tid = threadIdx.x;
    for (int i = tid; i < NG * D; i += 256) ps[i] = 0.f;
    __syncthreads();

    int w = (blockIdx.x * blockDim.x + tid) >> 5;
    int lane = tid & 31;
    float f[8];
#pragma unroll
    for (int j = 0; j < 8; j++) f[j] = 0.f;
    gather_node(w, lane, f);

    if (lane < 4) {
        int base = w * D + 8 * lane;
        float4 s0 = *(const float4*)&g_self[base];
        float4 s1 = *(const float4*)&g_self[base + 4];
        float4 b0 = *(const float4*)&bn[8 * lane];
        float4 b1 = *(const float4*)&bn[8 * lane + 4];
        float* pp = &ps[gid[w] * D + 8 * lane];
        atomicAdd(&pp[0], fmaxf(f[0] + s0.x + b0.x, 0.f));
        atomicAdd(&pp[1], fmaxf(f[1] + s0.y + b0.y, 0.f));
        atomicAdd(&pp[2], fmaxf(f[2] + s0.z + b0.z, 0.f));
        atomicAdd(&pp[3], fmaxf(f[3] + s0.w + b0.w, 0.f));
        atomicAdd(&pp[4], fmaxf(f[4] + s1.x + b1.x, 0.f));
        atomicAdd(&pp[5], fmaxf(f[5] + s1.y + b1.y, 0.f));
        atomicAdd(&pp[6], fmaxf(f[6] + s1.z + b1.z, 0.f));
        atomicAdd(&pp[7], fmaxf(f[7] + s1.w + b1.w, 0.f));
    }
    __syncthreads();
    for (int i = tid; i < NG * D; i += 256) {
        float v = ps[i];
        if (v != 0.f) atomicAdd(&g_pool[i], v);
    }
}

// ------------------------------------------------------------------
__global__ void mlp_kernel(const float* __restrict__ Wfc1, const float* __restrict__ bfc1,
                           const float* __restrict__ Wout, const float* __restrict__ bout,
                           float* __restrict__ out) {
    int g = threadIdx.x;
    if (g >= NG) return;
    float hv[D];
#pragma unroll
    for (int k = 0; k < D; k++) hv[k] = g_pool[g * D + k];
    float h2[8];
#pragma unroll
    for (int j = 0; j < 8; j++) {
        float s = bfc1[j];
#pragma unroll
        for (int k = 0; k < D; k++) s = fmaf(hv[k], Wfc1[k * 8 + j], s);
        h2[j] = fmaxf(s, 0.f);
    }
    float o[4];
    float m = -1e30f;
#pragma unroll
    for (int j = 0; j < 4; j++) {
        float s = bout[j];
#pragma unroll
        for (int k = 0; k < 8; k++) s = fmaf(h2[k], Wout[k * 4 + j], s);
        o[j] = fmaxf(s, 0.f);
        if (o[j] > m) m = o[j];
    }
    float e[4]; float sum = 0.f;
#pragma unroll
    for (int j = 0; j < 4; j++) { e[j] = expf(o[j] - m); sum += e[j]; }
#pragma unroll
    for (int j = 0; j < 4; j++) out[g * 4 + j] = e[j] / sum;
}

// ------------------------------------------------------------------
extern "C" void kernel_launch(void* const* d_in, const int* in_sizes, int n_in,
                              void* d_out, int out_size) {
    const float* x    = (const float*)d_in[0];
    const float* Wn0  = (const float*)d_in[1];
    const float* bn0  = (const float*)d_in[2];
    const float* Ws0  = (const float*)d_in[3];
    const float* Wn   = (const float*)d_in[4];
    const float* bn   = (const float*)d_in[5];
    const float* Ws   = (const float*)d_in[6];
    const float* Wfc1 = (const float*)d_in[7];
    const float* bfc1 = (const float*)d_in[8];
    const float* Wout = (const float*)d_in[9];
    const float* bout = (const float*)d_in[10];
    const int*   src  = (const int*)d_in[11];
    const int*   dst  = (const int*)d_in[12];
    const int*   gid  = (const int*)d_in[13];
    float* out = (float*)d_out;

    // Fork a side stream so the CSR build overlaps gemm0.
    cudaStream_t s2;
    cudaEvent_t ev_fork, ev_join;
    cudaStreamCreateWithFlags(&s2, cudaStreamNonBlocking);
    cudaEventCreateWithFlags(&ev_fork, cudaEventDisableTiming);
    cudaEventCreateWithFlags(&ev_join, cudaEventDisableTiming);

    cudaEventRecord(ev_fork, 0);
    cudaStreamWaitEvent(s2, ev_fork, 0);

    hist_kernel<<<(NE / 4 + 255) / 256, 256, 0, s2>>>(dst);
    scan_part<<<SCB, 512, 0, s2>>>();
    scan_mid<<<1, 256, 0, s2>>>();
    scan_add<<<SCB, 512, 0, s2>>>();
    scatter_kernel<<<(NE / 4 + 255) / 256, 256, 0, s2>>>(src, dst);
    cudaEventRecord(ev_join, s2);

    gemm0_kernel<<<(NN + 63) / 64, 64>>>(x, Wn0, Ws0);

    cudaStreamWaitEvent(0, ev_join, 0);

    agg_kernel<<<(NN * 32 + 255) / 256, 256>>>(bn0);
    for (int l = 0; l < 2; l++) {
        gemm_small_kernel<<<(NN + 63) / 64, 64>>>(Wn + l * D * D, Ws + l * D * D);
        agg_kernel<<<(NN * 32 + 255) / 256, 256>>>(bn + l * D);
    }
    // layer 3: transform + fused agg+pool
    gemm_small_kernel<<<(NN + 63) / 64, 64>>>(Wn + 2 * D * D, Ws + 2 * D * D);
    agg_pool_kernel<<<NN * 32 / 256, 256>>>(bn + 2 * D, gid);

    mlp_kernel<<<1, 64>>>(Wfc1, bfc1, Wout, bout, out);
    // stream/events intentionally not destroyed (capture-safe; ~3 calls total)
}